// round 4
// baseline (speedup 1.0000x reference)
#include <cuda_runtime.h>
#include <cuda_bf16.h>
#include <math.h>

#define Bn 16
#define Cn 64
#define Hn 256
#define HWn 65536

__device__ float g_x[Bn*Cn*HWn];       // activations [b][c][h][w] (in place)
__device__ float g_G[Bn*Cn*Hn*32];     // fwd w-DFT: [row][kx](re,im)
__device__ float g_F[Bn*Cn*1024];      // fwd spectrum [bc][s][kx][2]
__device__ float g_F2[Bn*Cn*1024];     // after spectral mix [bo][s][kx][2]
__device__ float g_Gi[Bn*Cn*8192];     // inv h-DFT [bo][kx][h](re,im)
__device__ float g_part[Bn*Cn*256];    // proj partial sums per (b,o,h)
__device__ float g_ct[256];
__device__ float g_st[256];
__device__ float2 g_cc2[256];
__device__ float2 g_ss2[256];
__device__ __nv_bfloat16 g_twG_hi[32*264], g_twG_lo[32*264];   // fwd-w B^T [kxri][w]
__device__ __nv_bfloat16 g_twF_hi[256*32], g_twF_lo[256*32];   // fuse  B^T [w][kxri]

__device__ __forceinline__ float gelu(float x) {
    return 0.5f * x * (1.0f + erff(x * 0.70710678f));
}

__device__ __forceinline__ float2 ffma2(float2 a, float2 b, float2 c) {
    float2 d;
    asm("fma.rn.f32x2 %0, %1, %2, %3;"
        : "=l"(*(unsigned long long*)&d)
        : "l"(*(unsigned long long*)&a),
          "l"(*(unsigned long long*)&b),
          "l"(*(unsigned long long*)&c));
    return d;
}

__device__ __forceinline__ void mma16816(float* d, unsigned a0, unsigned a1, unsigned a2, unsigned a3,
                                         unsigned b0, unsigned b1) {
    asm volatile("mma.sync.aligned.m16n8k16.row.col.f32.bf16.bf16.f32 "
                 "{%0,%1,%2,%3}, {%4,%5,%6,%7}, {%8,%9}, {%0,%1,%2,%3};"
                 : "+f"(d[0]), "+f"(d[1]), "+f"(d[2]), "+f"(d[3])
                 : "r"(a0), "r"(a1), "r"(a2), "r"(a3), "r"(b0), "r"(b1));
}

__device__ __forceinline__ void bsplit(float v, __nv_bfloat16* hi, __nv_bfloat16* lo) {
    __nv_bfloat16 h = __float2bfloat16_rn(v);
    *hi = h;
    *lo = __float2bfloat16_rn(v - __bfloat162float(h));
}

// ---------------- init: twiddle tables (fp32 + bf16-split planes) ----------------
__global__ void k_init() {
    int tid = threadIdx.x;
    {
        double s, c;
        sincospi((double)tid / 128.0, &s, &c);
        g_ct[tid] = (float)c;  g_st[tid] = (float)s;
        g_cc2[tid] = make_float2((float)c, (float)c);
        g_ss2[tid] = make_float2((float)s, (float)s);
    }
    // fuse B^T twiddle rows: [w][j], j=2kx -> cos, j=2kx+1 -> -sin of 2pi*kx*w/256
    for (int i = tid; i < 256 * 32; i += 256) {
        int w = i >> 5, j = i & 31, kx = j >> 1;
        double s, c;
        sincospi((double)((kx * w) & 255) / 128.0, &s, &c);
        float v = (float)((j & 1) ? -s : c);
        bsplit(v, &g_twF_hi[i], &g_twF_lo[i]);
    }
    // fwd-w B^T: [n][w] padded stride 264; n=2kx -> cos, n=2kx+1 -> -sin
    for (int i = tid; i < 32 * 264; i += 256) {
        int n = i / 264, w = i % 264;
        float v = 0.f;
        if (w < 256) {
            int kx = n >> 1;
            double s, c;
            sincospi((double)((kx * w) & 255) / 128.0, &s, &c);
            v = (float)((n & 1) ? -s : c);
        }
        bsplit(v, &g_twG_hi[i], &g_twG_lo[i]);
    }
}

// ---------------- lift: 15 -> 64 channels + gelu (scalar, R2) ----------------
__global__ void __launch_bounds__(256) k_lift(const float* __restrict__ grid,
                                              const float* __restrict__ lw,
                                              const float* __restrict__ lb) {
    __shared__ float sw[960], sb[64];
    for (int i = threadIdx.x; i < 960; i += 256) sw[i] = lw[i];
    if (threadIdx.x < 64) sb[threadIdx.x] = lb[threadIdx.x];
    __syncthreads();
    int p = blockIdx.x * 256 + threadIdx.x;
    int b = p >> 16, hw = p & 65535;
    float in[15];
    const float* gp = grid + b * 15 * HWn + hw;
    #pragma unroll
    for (int c = 0; c < 15; c++) in[c] = gp[c * HWn];
    float* xp = g_x + b * Cn * HWn + hw;
    for (int o = 0; o < 64; o++) {
        float a = sb[o];
        #pragma unroll
        for (int c = 0; c < 15; c++) a = fmaf(in[c], sw[o * 15 + c], a);
        xp[o * HWn] = gelu(a);
    }
}

// ---------------- fwd w-DFT via bf16-split MMA: [128 rows x 256] x [256 x 32] ----------------
__global__ void __launch_bounds__(128) k_fwd_w_mma() {
    extern __shared__ __nv_bfloat16 smw[];
    __nv_bfloat16* Ah = smw;              // [128][264]
    __nv_bfloat16* Al = Ah + 128 * 264;
    __nv_bfloat16* Bh = Al + 128 * 264;   // [32][264]
    __nv_bfloat16* Bl = Bh + 32 * 264;
    int tid = threadIdx.x;
    int r0 = blockIdx.x * 128;
    for (int i = tid; i < 128 * 256; i += 128) {
        int r = i >> 8, w = i & 255;
        float v = g_x[(r0 + r) * 256 + w];
        bsplit(v, &Ah[r * 264 + w], &Al[r * 264 + w]);
    }
    for (int i = tid; i < 32 * 264; i += 128) { Bh[i] = g_twG_hi[i]; Bl[i] = g_twG_lo[i]; }
    __syncthreads();
    int wid = tid >> 5, lane = tid & 31;
    int g = lane >> 2, t = lane & 3;
    int mrow0 = wid * 32;
    float D[2][4][4];
    #pragma unroll
    for (int mt = 0; mt < 2; mt++)
        #pragma unroll
        for (int nt = 0; nt < 4; nt++)
            #pragma unroll
            for (int j = 0; j < 4; j++) D[mt][nt][j] = 0.f;
    for (int k = 0; k < 256; k += 16) {
        unsigned ah[2][4], al[2][4];
        #pragma unroll
        for (int mt = 0; mt < 2; mt++) {
            int rb = (mrow0 + mt * 16 + g) * 264 + k + 2 * t;
            ah[mt][0] = *(const unsigned*)&Ah[rb];
            ah[mt][1] = *(const unsigned*)&Ah[rb + 8 * 264];
            ah[mt][2] = *(const unsigned*)&Ah[rb + 8];
            ah[mt][3] = *(const unsigned*)&Ah[rb + 8 * 264 + 8];
            al[mt][0] = *(const unsigned*)&Al[rb];
            al[mt][1] = *(const unsigned*)&Al[rb + 8 * 264];
            al[mt][2] = *(const unsigned*)&Al[rb + 8];
            al[mt][3] = *(const unsigned*)&Al[rb + 8 * 264 + 8];
        }
        #pragma unroll
        for (int nt = 0; nt < 4; nt++) {
            int nb = (nt * 8 + g) * 264 + k + 2 * t;
            unsigned bh0 = *(const unsigned*)&Bh[nb];
            unsigned bh1 = *(const unsigned*)&Bh[nb + 8];
            unsigned bl0 = *(const unsigned*)&Bl[nb];
            unsigned bl1 = *(const unsigned*)&Bl[nb + 8];
            #pragma unroll
            for (int mt = 0; mt < 2; mt++) {
                mma16816(D[mt][nt], ah[mt][0], ah[mt][1], ah[mt][2], ah[mt][3], bh0, bh1);
                mma16816(D[mt][nt], ah[mt][0], ah[mt][1], ah[mt][2], ah[mt][3], bl0, bl1);
                mma16816(D[mt][nt], al[mt][0], al[mt][1], al[mt][2], al[mt][3], bh0, bh1);
            }
        }
    }
    #pragma unroll
    for (int mt = 0; mt < 2; mt++) {
        int r = mrow0 + mt * 16 + g;
        #pragma unroll
        for (int nt = 0; nt < 4; nt++) {
            int c = nt * 8 + 2 * t;
            *(float2*)&g_G[(r0 + r) * 32 + c]     = make_float2(D[mt][nt][0], D[mt][nt][1]);
            *(float2*)&g_G[(r0 + r + 8) * 32 + c] = make_float2(D[mt][nt][2], D[mt][nt][3]);
        }
    }
}

// ---------------- fwd h-DFT (scalar, R2) ----------------
__global__ void __launch_bounds__(256) k_fwd_h() {
    __shared__ float Gs[8192];
    int tid = threadIdx.x, bc = blockIdx.x;
    const float* gp = g_G + bc * 8192;
    for (int i = tid; i < 8192; i += 256) Gs[i] = gp[i];
    __syncthreads();
    int s = tid >> 3, kq = tid & 7;
    int ky = (s < 16) ? s : s + 224;
    float cd = g_ct[ky], sd = -g_st[ky], cw = 1.f, sw = 0.f;
    float fr0 = 0.f, fi0 = 0.f, fr1 = 0.f, fi1 = 0.f;
    for (int h = 0; h < 256; h++) {
        float2 g0 = *(const float2*)&Gs[h * 32 + kq * 4];
        float2 g1 = *(const float2*)&Gs[h * 32 + kq * 4 + 2];
        fr0 = fmaf(g0.x, cw, fmaf(-g0.y, sw, fr0));
        fi0 = fmaf(g0.y, cw, fmaf( g0.x, sw, fi0));
        fr1 = fmaf(g1.x, cw, fmaf(-g1.y, sw, fr1));
        fi1 = fmaf(g1.y, cw, fmaf( g1.x, sw, fi1));
        float cn = cw * cd - sw * sd;
        sw = fmaf(cw, sd, sw * cd);  cw = cn;
    }
    int base = bc * 1024 + (s * 16 + kq * 2) * 2;
    g_F[base] = fr0; g_F[base + 1] = fi0; g_F[base + 2] = fr1; g_F[base + 3] = fi1;
}

// ---------------- spectral multiply (scalar, R2) ----------------
__global__ void __launch_bounds__(256) k_spec(const float* __restrict__ w1r, const float* __restrict__ w1i,
                                              const float* __restrict__ w2r, const float* __restrict__ w2i,
                                              int l) {
    __shared__ float Wr[4096], Wi[4096], Ar[1024], Ai[1024];
    int s = blockIdx.x >> 4, kx = blockIdx.x & 15;
    int m = (s < 16) ? s : s - 16;
    long off = (long)l * Cn * Cn * 256 + m * 16 + kx;
    const float* wr = ((s < 16) ? w1r : w2r) + off;
    const float* wi = ((s < 16) ? w1i : w2i) + off;
    for (int t = threadIdx.x; t < 4096; t += 256) { Wr[t] = wr[(long)t * 256]; Wi[t] = wi[(long)t * 256]; }
    int mo = (s * 16 + kx) * 2;
    for (int t = threadIdx.x; t < 1024; t += 256) { Ar[t] = g_F[t * 1024 + mo]; Ai[t] = g_F[t * 1024 + mo + 1]; }
    __syncthreads();
    int o = threadIdx.x & 63, bq = threadIdx.x >> 6;
    float orr[4], oii[4];
    #pragma unroll
    for (int u = 0; u < 4; u++) { orr[u] = 0.f; oii[u] = 0.f; }
    for (int i = 0; i < 64; i++) {
        float wrv = Wr[i * 64 + o], wiv = Wi[i * 64 + o];
        #pragma unroll
        for (int u = 0; u < 4; u++) {
            float arv = Ar[(bq * 4 + u) * 64 + i], aiv = Ai[(bq * 4 + u) * 64 + i];
            orr[u] = fmaf(arv, wrv, fmaf(-aiv, wiv, orr[u]));
            oii[u] = fmaf(arv, wiv, fmaf( aiv, wrv, oii[u]));
        }
    }
    #pragma unroll
    for (int u = 0; u < 4; u++) {
        int b = bq * 4 + u;
        g_F2[(b * 64 + o) * 1024 + mo]     = orr[u];
        g_F2[(b * 64 + o) * 1024 + mo + 1] = oii[u];
    }
}

// ---------------- inv h-DFT (scalar, P/Q packed, interleaved output) ----------------
__global__ void __launch_bounds__(256) k_inv_h() {
    __shared__ float Fs[1024];
    __shared__ float2 scc[256], sss[256];
    int tid = threadIdx.x, bo = blockIdx.x;
    const float* fp = g_F2 + bo * 1024;
    for (int i = tid; i < 1024; i += 256) Fs[i] = fp[i];
    scc[tid] = g_cc2[tid]; sss[tid] = g_ss2[tid];
    __syncthreads();
    int h = tid;
    float2 P[16], Q[16];
    #pragma unroll
    for (int k = 0; k < 16; k++) { P[k] = make_float2(0.f, 0.f); Q[k] = make_float2(0.f, 0.f); }
    #pragma unroll 2
    for (int s = 0; s < 32; s++) {
        int ky = (s < 16) ? s : s + 224;
        int idx = (ky * h) & 255;
        float2 cc = scc[idx], ss = sss[idx];
        #pragma unroll
        for (int q = 0; q < 8; q++) {
            float4 f4 = *(const float4*)&Fs[s * 32 + q * 4];
            float2 fa = make_float2(f4.x, f4.y), fb = make_float2(f4.z, f4.w);
            P[2 * q]     = ffma2(fa, cc, P[2 * q]);     Q[2 * q]     = ffma2(fa, ss, Q[2 * q]);
            P[2 * q + 1] = ffma2(fb, cc, P[2 * q + 1]); Q[2 * q + 1] = ffma2(fb, ss, Q[2 * q + 1]);
        }
    }
    float2* go = (float2*)g_Gi + bo * 4096 + h;
    #pragma unroll
    for (int k = 0; k < 16; k++) {
        float sc = (k == 0 ? 1.f : 2.f) * (1.f / 65536.f);
        go[k * 256] = make_float2((P[k].x - Q[k].y) * sc, (P[k].y + Q[k].x) * sc);
    }
}

// ---------------- fused inv w-DFT + skip + BN + gelu + residual via MMA ----------------
// per (b,h): D[64 o x 256 w] = A[64 x 96] x B[96 x 256]; A = [skw | Gi], B^T = [x^T | twiddles]
__global__ void __launch_bounds__(256) k_fuse_mma(const float* __restrict__ skw, const float* __restrict__ skb,
                                                  const float* __restrict__ bng, const float* __restrict__ bnb,
                                                  const float* __restrict__ bnm, const float* __restrict__ bnv,
                                                  int l) {
    extern __shared__ __nv_bfloat16 smf[];
    __nv_bfloat16* BTh = smf;                  // [256][104]
    __nv_bfloat16* BTl = BTh + 256 * 104;
    __nv_bfloat16* Ah  = BTl + 256 * 104;      // [64][104]
    __nv_bfloat16* Al  = Ah + 64 * 104;
    __shared__ float bnA[64], bnB2[64];
    int tid = threadIdx.x;
    int b = blockIdx.x >> 8, h = blockIdx.x & 255;
    float* xp = g_x + b * 64 * HWn + h * 256;
    for (int c = 0; c < 64; c++) {
        float v = xp[c * HWn + tid];
        bsplit(v, &BTh[tid * 104 + c], &BTl[tid * 104 + c]);
    }
    for (int i = tid; i < 256 * 32; i += 256) {
        int w = i >> 5, j = i & 31;
        BTh[w * 104 + 64 + j] = g_twF_hi[i];
        BTl[w * 104 + 64 + j] = g_twF_lo[i];
    }
    for (int i = tid; i < 4096; i += 256) {
        int o = i >> 6, c = i & 63;
        bsplit(skw[l * 4096 + i], &Ah[o * 104 + c], &Al[o * 104 + c]);
    }
    for (int i = tid; i < 1024; i += 256) {
        int o = i >> 4, kx = i & 15;
        float2 v = ((const float2*)g_Gi)[(b * 64 + o) * 4096 + kx * 256 + h];
        bsplit(v.x, &Ah[o * 104 + 64 + 2 * kx], &Al[o * 104 + 64 + 2 * kx]);
        bsplit(v.y, &Ah[o * 104 + 65 + 2 * kx], &Al[o * 104 + 65 + 2 * kx]);
    }
    if (tid < 64) {
        float A = bng[l * 64 + tid] * rsqrtf(bnv[l * 64 + tid] + 1e-5f);
        bnA[tid] = A;
        bnB2[tid] = fmaf(skb[l * 64 + tid] - bnm[l * 64 + tid], A, bnb[l * 64 + tid]);
    }
    __syncthreads();
    int wid = tid >> 5, lane = tid & 31;
    int g = lane >> 2, t = lane & 3;
    int mrow0 = (wid & 1) * 32, ncol0 = (wid >> 1) * 64;
    float D[2][8][4];
    #pragma unroll
    for (int mt = 0; mt < 2; mt++)
        #pragma unroll
        for (int nt = 0; nt < 8; nt++)
            #pragma unroll
            for (int j = 0; j < 4; j++) D[mt][nt][j] = 0.f;
    #pragma unroll
    for (int k = 0; k < 96; k += 16) {
        unsigned ah[2][4], al[2][4];
        #pragma unroll
        for (int mt = 0; mt < 2; mt++) {
            int rb = (mrow0 + mt * 16 + g) * 104 + k + 2 * t;
            ah[mt][0] = *(const unsigned*)&Ah[rb];
            ah[mt][1] = *(const unsigned*)&Ah[rb + 8 * 104];
            ah[mt][2] = *(const unsigned*)&Ah[rb + 8];
            ah[mt][3] = *(const unsigned*)&Ah[rb + 8 * 104 + 8];
            al[mt][0] = *(const unsigned*)&Al[rb];
            al[mt][1] = *(const unsigned*)&Al[rb + 8 * 104];
            al[mt][2] = *(const unsigned*)&Al[rb + 8];
            al[mt][3] = *(const unsigned*)&Al[rb + 8 * 104 + 8];
        }
        #pragma unroll
        for (int nt = 0; nt < 8; nt++) {
            int nb = (ncol0 + nt * 8 + g) * 104 + k + 2 * t;
            unsigned bh0 = *(const unsigned*)&BTh[nb];
            unsigned bh1 = *(const unsigned*)&BTh[nb + 8];
            unsigned bl0 = *(const unsigned*)&BTl[nb];
            unsigned bl1 = *(const unsigned*)&BTl[nb + 8];
            #pragma unroll
            for (int mt = 0; mt < 2; mt++) {
                mma16816(D[mt][nt], ah[mt][0], ah[mt][1], ah[mt][2], ah[mt][3], bh0, bh1);
                mma16816(D[mt][nt], ah[mt][0], ah[mt][1], ah[mt][2], ah[mt][3], bl0, bl1);
                mma16816(D[mt][nt], al[mt][0], al[mt][1], al[mt][2], al[mt][3], bh0, bh1);
            }
        }
    }
    #pragma unroll
    for (int mt = 0; mt < 2; mt++) {
        int rA = mrow0 + mt * 16 + g, rB = rA + 8;
        float aA = bnA[rA], bA = bnB2[rA];
        float aB = bnA[rB], bB = bnB2[rB];
        #pragma unroll
        for (int nt = 0; nt < 8; nt++) {
            int c = ncol0 + nt * 8 + 2 * t;
            float r0f = __bfloat162float(BTh[c * 104 + rA]) + __bfloat162float(BTl[c * 104 + rA]);
            float r1f = __bfloat162float(BTh[(c + 1) * 104 + rA]) + __bfloat162float(BTl[(c + 1) * 104 + rA]);
            float r2f = __bfloat162float(BTh[c * 104 + rB]) + __bfloat162float(BTl[c * 104 + rB]);
            float r3f = __bfloat162float(BTh[(c + 1) * 104 + rB]) + __bfloat162float(BTl[(c + 1) * 104 + rB]);
            float2 o0 = make_float2(gelu(fmaf(D[mt][nt][0], aA, bA)) + r0f,
                                    gelu(fmaf(D[mt][nt][1], aA, bA)) + r1f);
            float2 o1 = make_float2(gelu(fmaf(D[mt][nt][2], aB, bB)) + r2f,
                                    gelu(fmaf(D[mt][nt][3], aB, bB)) + r3f);
            *(float2*)&xp[rA * HWn + c] = o0;
            *(float2*)&xp[rB * HWn + c] = o1;
        }
    }
}

// ---------------- proj conv + gelu + partial mean via MMA ----------------
__global__ void __launch_bounds__(256) k_proj_mma(const float* __restrict__ pw, const float* __restrict__ pb) {
    extern __shared__ __nv_bfloat16 smp[];
    __nv_bfloat16* BTh = smp;                  // [256][72]
    __nv_bfloat16* BTl = BTh + 256 * 72;
    __nv_bfloat16* Ah  = BTl + 256 * 72;       // [64][72]
    __nv_bfloat16* Al  = Ah + 64 * 72;
    __shared__ float red[64][4];
    __shared__ float pbs[64];
    int tid = threadIdx.x;
    int b = blockIdx.x >> 8, h = blockIdx.x & 255;
    const float* xp = g_x + b * 64 * HWn + h * 256;
    for (int c = 0; c < 64; c++) {
        float v = xp[c * HWn + tid];
        bsplit(v, &BTh[tid * 72 + c], &BTl[tid * 72 + c]);
    }
    for (int i = tid; i < 4096; i += 256) {
        int o = i >> 6, c = i & 63;
        bsplit(pw[i], &Ah[o * 72 + c], &Al[o * 72 + c]);
    }
    if (tid < 64) pbs[tid] = pb[tid];
    __syncthreads();
    int wid = tid >> 5, lane = tid & 31;
    int g = lane >> 2, t = lane & 3;
    int mrow0 = (wid & 1) * 32, ncol0 = (wid >> 1) * 64;
    float D[2][8][4];
    #pragma unroll
    for (int mt = 0; mt < 2; mt++)
        #pragma unroll
        for (int nt = 0; nt < 8; nt++)
            #pragma unroll
            for (int j = 0; j < 4; j++) D[mt][nt][j] = 0.f;
    #pragma unroll
    for (int k = 0; k < 64; k += 16) {
        unsigned ah[2][4], al[2][4];
        #pragma unroll
        for (int mt = 0; mt < 2; mt++) {
            int rb = (mrow0 + mt * 16 + g) * 72 + k + 2 * t;
            ah[mt][0] = *(const unsigned*)&Ah[rb];
            ah[mt][1] = *(const unsigned*)&Ah[rb + 8 * 72];
            ah[mt][2] = *(const unsigned*)&Ah[rb + 8];
            ah[mt][3] = *(const unsigned*)&Ah[rb + 8 * 72 + 8];
            al[mt][0] = *(const unsigned*)&Al[rb];
            al[mt][1] = *(const unsigned*)&Al[rb + 8 * 72];
            al[mt][2] = *(const unsigned*)&Al[rb + 8];
            al[mt][3] = *(const unsigned*)&Al[rb + 8 * 72 + 8];
        }
        #pragma unroll
        for (int nt = 0; nt < 8; nt++) {
            int nb = (ncol0 + nt * 8 + g) * 72 + k + 2 * t;
            unsigned bh0 = *(const unsigned*)&BTh[nb];
            unsigned bh1 = *(const unsigned*)&BTh[nb + 8];
            unsigned bl0 = *(const unsigned*)&BTl[nb];
            unsigned bl1 = *(const unsigned*)&BTl[nb + 8];
            #pragma unroll
            for (int mt = 0; mt < 2; mt++) {
                mma16816(D[mt][nt], ah[mt][0], ah[mt][1], ah[mt][2], ah[mt][3], bh0, bh1);
                mma16816(D[mt][nt], ah[mt][0], ah[mt][1], ah[mt][2], ah[mt][3], bl0, bl1);
                mma16816(D[mt][nt], al[mt][0], al[mt][1], al[mt][2], al[mt][3], bh0, bh1);
            }
        }
    }
    #pragma unroll
    for (int mt = 0; mt < 2; mt++) {
        int rA = mrow0 + mt * 16 + g, rB = rA + 8;
        float pA = pbs[rA], pB = pbs[rB];
        float sA = 0.f, sB = 0.f;
        #pragma unroll
        for (int nt = 0; nt < 8; nt++) {
            sA += gelu(D[mt][nt][0] + pA) + gelu(D[mt][nt][1] + pA);
            sB += gelu(D[mt][nt][2] + pB) + gelu(D[mt][nt][3] + pB);
        }
        sA += __shfl_xor_sync(0xffffffffu, sA, 1);
        sA += __shfl_xor_sync(0xffffffffu, sA, 2);
        sB += __shfl_xor_sync(0xffffffffu, sB, 1);
        sB += __shfl_xor_sync(0xffffffffu, sB, 2);
        if (t == 0) {
            red[rA][wid >> 1] = sA;
            red[rB][wid >> 1] = sB;
        }
    }
    __syncthreads();
    if (tid < 64) {
        float s = red[tid][0] + red[tid][1] + red[tid][2] + red[tid][3];
        g_part[(b * 64 + tid) * 256 + h] = s;
    }
}

__global__ void __launch_bounds__(128) k_head(const float* __restrict__ env, const float* __restrict__ d1d,
    const float* __restrict__ dw1, const float* __restrict__ db1,
    const float* __restrict__ dw2, const float* __restrict__ db2,
    const float* __restrict__ dw3, const float* __restrict__ db3,
    const float* __restrict__ iw1, const float* __restrict__ ib1,
    const float* __restrict__ iw2, const float* __restrict__ ib2,
    const float* __restrict__ iw3, const float* __restrict__ ib3,
    float* __restrict__ out) {
    __shared__ float feat[108], h1[128], h2[64];
    int b = blockIdx.x, t = threadIdx.x;
    if (t < 64) {
        float s = 0.f;
        const float* pp = g_part + (b * 64 + t) * 256;
        for (int h = 0; h < 256; h++) s += pp[h];
        feat[t] = s * (1.0f / 65536.0f);
    } else if (t < 104) feat[t] = env[b * 40 + t - 64];
    else if (t < 108)   feat[t] = d1d[b * 4 + t - 104];
    __syncthreads();
    { float a = db1[t];
      for (int k = 0; k < 108; k++) a = fmaf(feat[k], dw1[t * 108 + k], a);
      h1[t] = gelu(a); }
    __syncthreads();
    if (t < 64) { float a = db2[t];
      for (int k = 0; k < 128; k++) a = fmaf(h1[k], dw2[t * 128 + k], a);
      h2[t] = gelu(a); }
    __syncthreads();
    if (t < 8) { float a = db3[t];
      for (int k = 0; k < 64; k++) a = fmaf(h2[k], dw3[t * 64 + k], a);
      out[b * 8 + t] = a; }
    __syncthreads();
    { float a = ib1[t];
      for (int k = 0; k < 108; k++) a = fmaf(feat[k], iw1[t * 108 + k], a);
      h1[t] = gelu(a); }
    __syncthreads();
    if (t < 64) { float a = ib2[t];
      for (int k = 0; k < 128; k++) a = fmaf(h1[k], iw2[t * 128 + k], a);
      h2[t] = gelu(a); }
    __syncthreads();
    if (t < 4) { float a = ib3[t];
      for (int k = 0; k < 64; k++) a = fmaf(h2[k], iw3[t * 64 + k], a);
      out[128 + b * 4 + t] = a; }
}

extern "C" void kernel_launch(void* const* d_in, const int* in_sizes, int n_in,
                              void* d_out, int out_size) {
    const float* grid_in = (const float*)d_in[0];
    const float* env  = (const float*)d_in[1];
    const float* d1d  = (const float*)d_in[2];
    const float* lw   = (const float*)d_in[3];
    const float* lb   = (const float*)d_in[4];
    const float* w1r  = (const float*)d_in[5];
    const float* w1i  = (const float*)d_in[6];
    const float* w2r  = (const float*)d_in[7];
    const float* w2i  = (const float*)d_in[8];
    const float* skw  = (const float*)d_in[9];
    const float* skb  = (const float*)d_in[10];
    const float* bng  = (const float*)d_in[11];
    const float* bnb  = (const float*)d_in[12];
    const float* bnm  = (const float*)d_in[13];
    const float* bnv  = (const float*)d_in[14];
    const float* pw   = (const float*)d_in[15];
    const float* pb   = (const float*)d_in[16];
    const float* dw1  = (const float*)d_in[17];
    const float* db1  = (const float*)d_in[18];
    const float* dw2  = (const float*)d_in[19];
    const float* db2  = (const float*)d_in[20];
    const float* dw3  = (const float*)d_in[21];
    const float* db3  = (const float*)d_in[22];
    const float* iw1  = (const float*)d_in[23];
    const float* ib1  = (const float*)d_in[24];
    const float* iw2  = (const float*)d_in[25];
    const float* ib2  = (const float*)d_in[26];
    const float* iw3  = (const float*)d_in[27];
    const float* ib3  = (const float*)d_in[28];
    float* out = (float*)d_out;

    static bool attr_done = false;
    if (!attr_done) {
        cudaFuncSetAttribute(k_fwd_w_mma, cudaFuncAttributeMaxDynamicSharedMemorySize, 168960);
        cudaFuncSetAttribute(k_fuse_mma,  cudaFuncAttributeMaxDynamicSharedMemorySize, 133120);
        cudaFuncSetAttribute(k_proj_mma,  cudaFuncAttributeMaxDynamicSharedMemorySize, 92160);
        attr_done = true;
    }

    k_init<<<1, 256>>>();
    k_lift<<<4096, 256>>>(grid_in, lw, lb);
    for (int l = 0; l < 4; l++) {
        k_fwd_w_mma<<<2048, 128, 168960>>>();
        k_fwd_h<<<1024, 256>>>();
        k_spec<<<512, 256>>>(w1r, w1i, w2r, w2i, l);
        k_inv_h<<<1024, 256>>>();
        k_fuse_mma<<<4096, 256, 133120>>>(skw, skb, bng, bnb, bnm, bnv, l);
    }
    k_proj_mma<<<4096, 256, 92160>>>(pw, pb);
    k_head<<<16, 128>>>(env, d1d, dw1, db1, dw2, db2, dw3, db3,
                        iw1, ib1, iw2, ib2, iw3, ib3, out);
}

// round 6
// speedup vs baseline: 1.6314x; 1.6314x over previous
#include <cuda_runtime.h>
#include <math.h>

#define Bn 16
#define Cn 64
#define Hn 256
#define HWn 65536

__device__ float g_x[Bn*Cn*HWn];       // activations [b][c][h][w] (in place)
__device__ float g_G[Bn*Cn*Hn*32];     // fwd w-DFT: [row][kx](re,im)
__device__ float g_F[Bn*Cn*1024];      // fwd spectrum [bc][s][kx][2]
__device__ float g_F2[Bn*Cn*1024];     // after spectral mix [bo][s][kx][2]
__device__ float g_Gi[Bn*Cn*8192];     // inv h-DFT [bo][kx][h](re,im) interleaved
__device__ float g_part[Bn*Cn*256];    // proj partial sums per (b,o,h)
__device__ float g_ct[256];
__device__ float g_st[256];
__device__ float2 g_cc2[256];
__device__ float2 g_ss2[256];

__device__ __forceinline__ float gelu(float x) {
    return 0.5f * x * (1.0f + erff(x * 0.70710678f));
}

__device__ __forceinline__ float2 ffma2(float2 a, float2 b, float2 c) {
    float2 d;
    asm("fma.rn.f32x2 %0, %1, %2, %3;"
        : "=l"(*(unsigned long long*)&d)
        : "l"(*(unsigned long long*)&a),
          "l"(*(unsigned long long*)&b),
          "l"(*(unsigned long long*)&c));
    return d;
}

// ---------------- compile-time twiddles (forced constant-fold via templates) ----------------
constexpr double TPI_ = 3.141592653589793238462643383279502884;
constexpr double tcos_(double x) {
    double t = 1.0, s = 1.0;
    for (int i = 1; i <= 16; i++) { t = -t * x * x / ((2.0 * i - 1.0) * (2.0 * i)); s += t; }
    return s;
}
constexpr double tsin_(double x) {
    double t = x, s = x;
    for (int i = 1; i <= 16; i++) { t = -t * x * x / ((2.0 * i) * (2.0 * i + 1.0)); s += t; }
    return s;
}
constexpr double ang_(int n) { return ((n <= 128) ? n : n - 256) * (TPI_ / 128.0); }
template<int N> struct TwN {
    static constexpr float C = (float)tcos_(ang_(N));      // cos(2pi N/256)
    static constexpr float S = (float)(-tsin_(ang_(N)));   // -sin(2pi N/256)
};

// inner kx loop: acc[k] += x * e^{-2pi i (W*k)/256}, all twiddles immediate
template<int W, int K> struct KL {
    static __device__ __forceinline__ void run(float x, float2* a) {
        constexpr int N = (W * K) & 255;
        a[K].x = fmaf(x, TwN<N>::C, a[K].x);
        a[K].y = fmaf(x, TwN<N>::S, a[K].y);
        KL<W, K + 1>::run(x, a);
    }
};
template<int W> struct KL<W, 16> {
    static __device__ __forceinline__ void run(float, float2*) {}
};
// j loop over 32 x-values of a chunk
template<int W0, int J> struct JL {
    static __device__ __forceinline__ void run(const float* xr, float2* a) {
        KL<W0 + J, 0>::run(xr[J], a);
        JL<W0, J + 1>::run(xr, a);
    }
};
template<int W0> struct JL<W0, 32> {
    static __device__ __forceinline__ void run(const float*, float2*) {}
};

template<int CC>
__device__ __forceinline__ void fw_chunk(int tid, int r0, float* xs, float2* acc) {
    __syncthreads();
    #pragma unroll 4
    for (int i = tid; i < 2048; i += 256) {
        int r = i >> 3, jq = (i & 7) * 4;
        float4 v = *(const float4*)&g_x[(r0 + r) * 256 + CC * 32 + jq];
        *(float4*)&xs[r * 36 + jq] = v;
    }
    __syncthreads();
    JL<CC * 32, 0>::run(xs + tid * 36, acc);
}

// ---------------- fwd w-DFT: thread-per-row, FFMA-imm twiddles ----------------
__global__ void __launch_bounds__(256) k_fwd_w_imm() {
    __shared__ float xs[256 * 36];
    int tid = threadIdx.x, r0 = blockIdx.x * 256;
    float2 acc[16];
    #pragma unroll
    for (int k = 0; k < 16; k++) acc[k] = make_float2(0.f, 0.f);
    fw_chunk<0>(tid, r0, xs, acc);
    fw_chunk<1>(tid, r0, xs, acc);
    fw_chunk<2>(tid, r0, xs, acc);
    fw_chunk<3>(tid, r0, xs, acc);
    fw_chunk<4>(tid, r0, xs, acc);
    fw_chunk<5>(tid, r0, xs, acc);
    fw_chunk<6>(tid, r0, xs, acc);
    fw_chunk<7>(tid, r0, xs, acc);
    float* gp = g_G + (r0 + tid) * 32;
    #pragma unroll
    for (int k = 0; k < 8; k++) {
        float4 v = make_float4(acc[2 * k].x, acc[2 * k].y, acc[2 * k + 1].x, acc[2 * k + 1].y);
        *(float4*)&gp[4 * k] = v;
    }
}

// ---------------- init: fp32 twiddle tables ----------------
__global__ void k_init() {
    int tid = threadIdx.x;
    double s, c;
    sincospi((double)tid / 128.0, &s, &c);
    g_ct[tid] = (float)c;  g_st[tid] = (float)s;
    g_cc2[tid] = make_float2((float)c, (float)c);
    g_ss2[tid] = make_float2((float)s, (float)s);
}

// ---------------- lift (R2 scalar) ----------------
__global__ void __launch_bounds__(256) k_lift(const float* __restrict__ grid,
                                              const float* __restrict__ lw,
                                              const float* __restrict__ lb) {
    __shared__ float sw[960], sb[64];
    for (int i = threadIdx.x; i < 960; i += 256) sw[i] = lw[i];
    if (threadIdx.x < 64) sb[threadIdx.x] = lb[threadIdx.x];
    __syncthreads();
    int p = blockIdx.x * 256 + threadIdx.x;
    int b = p >> 16, hw = p & 65535;
    float in[15];
    const float* gp = grid + b * 15 * HWn + hw;
    #pragma unroll
    for (int c = 0; c < 15; c++) in[c] = gp[c * HWn];
    float* xp = g_x + b * Cn * HWn + hw;
    for (int o = 0; o < 64; o++) {
        float a = sb[o];
        #pragma unroll
        for (int c = 0; c < 15; c++) a = fmaf(in[c], sw[o * 15 + c], a);
        xp[o * HWn] = gelu(a);
    }
}

// ---------------- fwd h-DFT (R2 scalar, measured 43.9us) ----------------
__global__ void __launch_bounds__(256) k_fwd_h() {
    __shared__ float Gs[8192];
    int tid = threadIdx.x, bc = blockIdx.x;
    const float* gp = g_G + bc * 8192;
    for (int i = tid; i < 8192; i += 256) Gs[i] = gp[i];
    __syncthreads();
    int s = tid >> 3, kq = tid & 7;
    int ky = (s < 16) ? s : s + 224;
    float cd = g_ct[ky], sd = -g_st[ky], cw = 1.f, sw = 0.f;
    float fr0 = 0.f, fi0 = 0.f, fr1 = 0.f, fi1 = 0.f;
    for (int h = 0; h < 256; h++) {
        float2 g0 = *(const float2*)&Gs[h * 32 + kq * 4];
        float2 g1 = *(const float2*)&Gs[h * 32 + kq * 4 + 2];
        fr0 = fmaf(g0.x, cw, fmaf(-g0.y, sw, fr0));
        fi0 = fmaf(g0.y, cw, fmaf( g0.x, sw, fi0));
        fr1 = fmaf(g1.x, cw, fmaf(-g1.y, sw, fr1));
        fi1 = fmaf(g1.y, cw, fmaf( g1.x, sw, fi1));
        float cn = cw * cd - sw * sd;
        sw = fmaf(cw, sd, sw * cd);  cw = cn;
    }
    int base = bc * 1024 + (s * 16 + kq * 2) * 2;
    g_F[base] = fr0; g_F[base + 1] = fi0; g_F[base + 2] = fr1; g_F[base + 3] = fi1;
}

// ---------------- spectral multiply (R2 scalar) ----------------
__global__ void __launch_bounds__(256) k_spec(const float* __restrict__ w1r, const float* __restrict__ w1i,
                                              const float* __restrict__ w2r, const float* __restrict__ w2i,
                                              int l) {
    __shared__ float Wr[4096], Wi[4096], Ar[1024], Ai[1024];
    int s = blockIdx.x >> 4, kx = blockIdx.x & 15;
    int m = (s < 16) ? s : s - 16;
    long off = (long)l * Cn * Cn * 256 + m * 16 + kx;
    const float* wr = ((s < 16) ? w1r : w2r) + off;
    const float* wi = ((s < 16) ? w1i : w2i) + off;
    for (int t = threadIdx.x; t < 4096; t += 256) { Wr[t] = wr[(long)t * 256]; Wi[t] = wi[(long)t * 256]; }
    int mo = (s * 16 + kx) * 2;
    for (int t = threadIdx.x; t < 1024; t += 256) { Ar[t] = g_F[t * 1024 + mo]; Ai[t] = g_F[t * 1024 + mo + 1]; }
    __syncthreads();
    int o = threadIdx.x & 63, bq = threadIdx.x >> 6;
    float orr[4], oii[4];
    #pragma unroll
    for (int u = 0; u < 4; u++) { orr[u] = 0.f; oii[u] = 0.f; }
    for (int i = 0; i < 64; i++) {
        float wrv = Wr[i * 64 + o], wiv = Wi[i * 64 + o];
        #pragma unroll
        for (int u = 0; u < 4; u++) {
            float arv = Ar[(bq * 4 + u) * 64 + i], aiv = Ai[(bq * 4 + u) * 64 + i];
            orr[u] = fmaf(arv, wrv, fmaf(-aiv, wiv, orr[u]));
            oii[u] = fmaf(arv, wiv, fmaf( aiv, wrv, oii[u]));
        }
    }
    #pragma unroll
    for (int u = 0; u < 4; u++) {
        int b = bq * 4 + u;
        g_F2[(b * 64 + o) * 1024 + mo]     = orr[u];
        g_F2[(b * 64 + o) * 1024 + mo + 1] = oii[u];
    }
}

// ---------------- inv h-DFT (packed, interleaved float2 output) ----------------
__global__ void __launch_bounds__(256) k_inv_h() {
    __shared__ float Fs[1024];
    __shared__ float2 scc[256], sss[256];
    int tid = threadIdx.x, bo = blockIdx.x;
    const float* fp = g_F2 + bo * 1024;
    for (int i = tid; i < 1024; i += 256) Fs[i] = fp[i];
    scc[tid] = g_cc2[tid]; sss[tid] = g_ss2[tid];
    __syncthreads();
    int h = tid;
    float2 P[16], Q[16];
    #pragma unroll
    for (int k = 0; k < 16; k++) { P[k] = make_float2(0.f, 0.f); Q[k] = make_float2(0.f, 0.f); }
    #pragma unroll 2
    for (int s = 0; s < 32; s++) {
        int ky = (s < 16) ? s : s + 224;
        int idx = (ky * h) & 255;
        float2 cc = scc[idx], ss = sss[idx];
        #pragma unroll
        for (int q = 0; q < 8; q++) {
            float4 f4 = *(const float4*)&Fs[s * 32 + q * 4];
            float2 fa = make_float2(f4.x, f4.y), fb = make_float2(f4.z, f4.w);
            P[2 * q]     = ffma2(fa, cc, P[2 * q]);     Q[2 * q]     = ffma2(fa, ss, Q[2 * q]);
            P[2 * q + 1] = ffma2(fb, cc, P[2 * q + 1]); Q[2 * q + 1] = ffma2(fb, ss, Q[2 * q + 1]);
        }
    }
    float2* go = (float2*)g_Gi + bo * 4096 + h;
    #pragma unroll
    for (int k = 0; k < 16; k++) {
        float sc = (k == 0 ? 1.f : 2.f) * (1.f / 65536.f);
        go[k * 256] = make_float2((P[k].x - Q[k].y) * sc, (P[k].y + Q[k].x) * sc);
    }
}

// ---------------- fused inv w-DFT + skip conv + BN + gelu + residual (f32x2-packed, R3) ----------------
__global__ void __launch_bounds__(256, 2) k_fuse(const float* __restrict__ skw, const float* __restrict__ skb,
                                                 const float* __restrict__ bng, const float* __restrict__ bnb,
                                                 const float* __restrict__ bnm, const float* __restrict__ bnv,
                                                 int l) {
    extern __shared__ float sm[];
    float* xs   = sm;              // 16896 = 64*264
    float* swt  = xs + 16896;      // 4096: [c][o]
    float* gis  = swt + 4096;      // 2048: [kx][ri][o], ri=1 negated
    float* ctb  = gis + 2048;      // 256
    float* stb  = ctb + 256;       // 256
    float* bnA  = stb + 256;       // 64
    float* bnB  = bnA + 64;        // 64
    float* sbbv = bnB + 64;        // 64
    int tid = threadIdx.x;
    int b = blockIdx.x >> 8, h = blockIdx.x & 255;
    float* xp = g_x + b * 64 * HWn + h * 256;
    for (int c = 0; c < 64; c++) xs[c * 264 + tid] = xp[c * HWn + tid];
    for (int i = tid; i < 4096; i += 256) {
        int o = i >> 6, c = i & 63;
        swt[c * 64 + o] = skw[l * 4096 + i];
    }
    for (int i = tid; i < 1024; i += 256) {
        int o = i >> 4, kx = i & 15;
        float2 v = ((const float2*)g_Gi)[(b * 64 + o) * 4096 + kx * 256 + h];
        gis[(kx * 2) * 64 + o]     = v.x;
        gis[(kx * 2 + 1) * 64 + o] = -v.y;
    }
    ctb[tid] = g_ct[tid];  stb[tid] = g_st[tid];
    if (tid < 64) {
        float A = bng[l * 64 + tid] * rsqrtf(bnv[l * 64 + tid] + 1e-5f);
        bnA[tid] = A;
        bnB[tid] = fmaf(-bnm[l * 64 + tid], A, bnb[l * 64 + tid]);
        sbbv[tid] = skb[l * 64 + tid];
    }
    __syncthreads();
    int wb = (tid & 63) * 4, ob = (tid >> 6) * 16;
    float2 acc[8][4];
    #pragma unroll
    for (int ip = 0; ip < 8; ip++) {
        float2 bias = *(const float2*)&sbbv[ob + ip * 2];
        acc[ip][0] = bias; acc[ip][1] = bias; acc[ip][2] = bias; acc[ip][3] = bias;
    }
    // skip conv (o-pair packed)
    for (int c = 0; c < 64; c++) {
        float4 xv = *(const float4*)&xs[c * 264 + wb];
        float2 x0 = make_float2(xv.x, xv.x), x1 = make_float2(xv.y, xv.y);
        float2 x2 = make_float2(xv.z, xv.z), x3 = make_float2(xv.w, xv.w);
        #pragma unroll
        for (int ip = 0; ip < 8; ip++) {
            float2 wv = *(const float2*)&swt[c * 64 + ob + ip * 2];
            acc[ip][0] = ffma2(x0, wv, acc[ip][0]);
            acc[ip][1] = ffma2(x1, wv, acc[ip][1]);
            acc[ip][2] = ffma2(x2, wv, acc[ip][2]);
            acc[ip][3] = ffma2(x3, wv, acc[ip][3]);
        }
    }
    // inverse w-DFT via per-thread twiddle recurrence over kx
    float dc[4], ds[4], tc_[4], ts_[4];
    #pragma unroll
    for (int j = 0; j < 4; j++) {
        dc[j] = ctb[wb + j];  ds[j] = stb[wb + j];
        tc_[j] = 1.f;  ts_[j] = 0.f;
    }
    #pragma unroll 4
    for (int kx = 0; kx < 16; kx++) {
        float2 cc0 = make_float2(tc_[0], tc_[0]), ss0 = make_float2(ts_[0], ts_[0]);
        float2 cc1 = make_float2(tc_[1], tc_[1]), ss1 = make_float2(ts_[1], ts_[1]);
        float2 cc2 = make_float2(tc_[2], tc_[2]), ss2 = make_float2(ts_[2], ts_[2]);
        float2 cc3 = make_float2(tc_[3], tc_[3]), ss3 = make_float2(ts_[3], ts_[3]);
        #pragma unroll
        for (int ip = 0; ip < 8; ip++) {
            float2 gr = *(const float2*)&gis[(kx * 2) * 64 + ob + ip * 2];
            float2 gi = *(const float2*)&gis[(kx * 2 + 1) * 64 + ob + ip * 2];
            acc[ip][0] = ffma2(gr, cc0, acc[ip][0]);  acc[ip][0] = ffma2(gi, ss0, acc[ip][0]);
            acc[ip][1] = ffma2(gr, cc1, acc[ip][1]);  acc[ip][1] = ffma2(gi, ss1, acc[ip][1]);
            acc[ip][2] = ffma2(gr, cc2, acc[ip][2]);  acc[ip][2] = ffma2(gi, ss2, acc[ip][2]);
            acc[ip][3] = ffma2(gr, cc3, acc[ip][3]);  acc[ip][3] = ffma2(gi, ss3, acc[ip][3]);
        }
        #pragma unroll
        for (int j = 0; j < 4; j++) {
            float nc = tc_[j] * dc[j] - ts_[j] * ds[j];
            ts_[j] = fmaf(tc_[j], ds[j], ts_[j] * dc[j]);
            tc_[j] = nc;
        }
    }
    // epilogue: BN + gelu + residual
    #pragma unroll
    for (int ip = 0; ip < 8; ip++) {
        int o0 = ob + ip * 2, o1 = o0 + 1;
        float A0 = bnA[o0], B0 = bnB[o0], A1 = bnA[o1], B1 = bnB[o1];
        float4 r0, r1;
        r0.x = gelu(fmaf(acc[ip][0].x, A0, B0)) + xs[o0 * 264 + wb];
        r0.y = gelu(fmaf(acc[ip][1].x, A0, B0)) + xs[o0 * 264 + wb + 1];
        r0.z = gelu(fmaf(acc[ip][2].x, A0, B0)) + xs[o0 * 264 + wb + 2];
        r0.w = gelu(fmaf(acc[ip][3].x, A0, B0)) + xs[o0 * 264 + wb + 3];
        r1.x = gelu(fmaf(acc[ip][0].y, A1, B1)) + xs[o1 * 264 + wb];
        r1.y = gelu(fmaf(acc[ip][1].y, A1, B1)) + xs[o1 * 264 + wb + 1];
        r1.z = gelu(fmaf(acc[ip][2].y, A1, B1)) + xs[o1 * 264 + wb + 2];
        r1.w = gelu(fmaf(acc[ip][3].y, A1, B1)) + xs[o1 * 264 + wb + 3];
        *(float4*)&xp[o0 * HWn + wb] = r0;
        *(float4*)&xp[o1 * HWn + wb] = r1;
    }
}

// ---------------- proj conv + gelu + partial mean (R2 scalar) ----------------
__global__ void __launch_bounds__(256) k_proj(const float* __restrict__ pw, const float* __restrict__ pb) {
    __shared__ float pws[4096], pbs[64], wsum[64][8];
    int tid = threadIdx.x;
    int b = blockIdx.x >> 8, h = blockIdx.x & 255;
    for (int i = tid; i < 4096; i += 256) pws[i] = pw[i];
    if (tid < 64) pbs[tid] = pb[tid];
    __syncthreads();
    const float* xp = g_x + b * 64 * HWn + h * 256 + tid;
    float xv[64];
    #pragma unroll
    for (int c = 0; c < 64; c++) xv[c] = xp[c * HWn];
    int lane = tid & 31, wid = tid >> 5;
    for (int o = 0; o < 64; o++) {
        float a = pbs[o];
        #pragma unroll
        for (int c = 0; c < 64; c++) a = fmaf(xv[c], pws[o * 64 + c], a);
        a = gelu(a);
        #pragma unroll
        for (int off = 16; off; off >>= 1) a += __shfl_down_sync(0xffffffffu, a, off);
        if (lane == 0) wsum[o][wid] = a;
    }
    __syncthreads();
    if (tid < 64) {
        float s = 0.f;
        #pragma unroll
        for (int j = 0; j < 8; j++) s += wsum[tid][j];
        g_part[(b * 64 + tid) * 256 + h] = s;
    }
}

__global__ void __launch_bounds__(128) k_head(const float* __restrict__ env, const float* __restrict__ d1d,
    const float* __restrict__ dw1, const float* __restrict__ db1,
    const float* __restrict__ dw2, const float* __restrict__ db2,
    const float* __restrict__ dw3, const float* __restrict__ db3,
    const float* __restrict__ iw1, const float* __restrict__ ib1,
    const float* __restrict__ iw2, const float* __restrict__ ib2,
    const float* __restrict__ iw3, const float* __restrict__ ib3,
    float* __restrict__ out) {
    __shared__ float feat[108], h1[128], h2[64];
    int b = blockIdx.x, t = threadIdx.x;
    if (t < 64) {
        float s = 0.f;
        const float* pp = g_part + (b * 64 + t) * 256;
        for (int h = 0; h < 256; h++) s += pp[h];
        feat[t] = s * (1.0f / 65536.0f);
    } else if (t < 104) feat[t] = env[b * 40 + t - 64];
    else if (t < 108)   feat[t] = d1d[b * 4 + t - 104];
    __syncthreads();
    { float a = db1[t];
      for (int k = 0; k < 108; k++) a = fmaf(feat[k], dw1[t * 108 + k], a);
      h1[t] = gelu(a); }
    __syncthreads();
    if (t < 64) { float a = db2[t];
      for (int k = 0; k < 128; k++) a = fmaf(h1[k], dw2[t * 128 + k], a);
      h2[t] = gelu(a); }
    __syncthreads();
    if (t < 8) { float a = db3[t];
      for (int k = 0; k < 64; k++) a = fmaf(h2[k], dw3[t * 64 + k], a);
      out[b * 8 + t] = a; }
    __syncthreads();
    { float a = ib1[t];
      for (int k = 0; k < 108; k++) a = fmaf(feat[k], iw1[t * 108 + k], a);
      h1[t] = gelu(a); }
    __syncthreads();
    if (t < 64) { float a = ib2[t];
      for (int k = 0; k < 128; k++) a = fmaf(h1[k], iw2[t * 128 + k], a);
      h2[t] = gelu(a); }
    __syncthreads();
    if (t < 4) { float a = ib3[t];
      for (int k = 0; k < 64; k++) a = fmaf(h2[k], iw3[t * 64 + k], a);
      out[128 + b * 4 + t] = a; }
}

extern "C" void kernel_launch(void* const* d_in, const int* in_sizes, int n_in,
                              void* d_out, int out_size) {
    const float* grid_in = (const float*)d_in[0];
    const float* env  = (const float*)d_in[1];
    const float* d1d  = (const float*)d_in[2];
    const float* lw   = (const float*)d_in[3];
    const float* lb   = (const float*)d_in[4];
    const float* w1r  = (const float*)d_in[5];
    const float* w1i  = (const float*)d_in[6];
    const float* w2r  = (const float*)d_in[7];
    const float* w2i  = (const float*)d_in[8];
    const float* skw  = (const float*)d_in[9];
    const float* skb  = (const float*)d_in[10];
    const float* bng  = (const float*)d_in[11];
    const float* bnb  = (const float*)d_in[12];
    const float* bnm  = (const float*)d_in[13];
    const float* bnv  = (const float*)d_in[14];
    const float* pw   = (const float*)d_in[15];
    const float* pb   = (const float*)d_in[16];
    const float* dw1  = (const float*)d_in[17];
    const float* db1  = (const float*)d_in[18];
    const float* dw2  = (const float*)d_in[19];
    const float* db2  = (const float*)d_in[20];
    const float* dw3  = (const float*)d_in[21];
    const float* db3  = (const float*)d_in[22];
    const float* iw1  = (const float*)d_in[23];
    const float* ib1  = (const float*)d_in[24];
    const float* iw2  = (const float*)d_in[25];
    const float* ib2  = (const float*)d_in[26];
    const float* iw3  = (const float*)d_in[27];
    const float* ib3  = (const float*)d_in[28];
    float* out = (float*)d_out;

    static bool attr_done = false;
    if (!attr_done) {
        cudaFuncSetAttribute(k_fuse, cudaFuncAttributeMaxDynamicSharedMemorySize, 94976);
        attr_done = true;
    }

    k_init<<<1, 256>>>();
    k_lift<<<4096, 256>>>(grid_in, lw, lb);
    for (int l = 0; l < 4; l++) {
        k_fwd_w_imm<<<1024, 256>>>();
        k_fwd_h<<<1024, 256>>>();
        k_spec<<<512, 256>>>(w1r, w1i, w2r, w2i, l);
        k_inv_h<<<1024, 256>>>();
        k_fuse<<<4096, 256, 94976>>>(skw, skb, bng, bnb, bnm, bnv, l);
    }
    k_proj<<<4096, 256>>>(pw, pb);
    k_head<<<16, 128>>>(env, d1d, dw1, db1, dw2, db2, dw3, db3,
                        iw1, ib1, iw2, ib2, iw3, ib3, out);
}